// round 6
// baseline (speedup 1.0000x reference)
#include <cuda_runtime.h>
#include <math.h>

// Problem constants
#define Bn   2
#define Tn   2048
#define En   1024
#define HQn  16
#define HKVn 4
#define Dn   64
#define Gn   4
#define MR   (Bn*Tn)            // 4096 rows
#define KVW  (HKVn*Dn)          // 256
#define YELEMS   (MR*En)                         // 4,194,304
#define ATTELEMS (134217728LL)                   // B*G*HKV*T*T

// Scratch (static device globals: allocation-free at run time)
__device__ float g_q[MR*En];
__device__ float g_k[MR*KVW];
__device__ float g_v[MR*KVW];
__device__ float g_y[MR*En];
// Full attention-matrix scratch for when d_out does NOT include att_weights.
__device__ float g_att[134217728];

#define NEG_INF __int_as_float(0xff800000)

// ---------------------------------------------------------------------------
// Generic SGEMM + bias: C[M,N] = A[M,K] @ B[K,N] + bias[N]
// 64x64 tile, BK=16, 256 threads, 4x4 micro-tile per thread.
// ---------------------------------------------------------------------------
__global__ void sgemm_bias(const float* __restrict__ A, const float* __restrict__ B,
                           const float* __restrict__ bias, float* __restrict__ C,
                           int M, int N, int K) {
    __shared__ float As[64][17];   // [m][kk], padded
    __shared__ float Bs[16][64];   // [kk][n]
    const int bm = blockIdx.y * 64;
    const int bn = blockIdx.x * 64;
    const int tx = threadIdx.x & 15;
    const int ty = threadIdx.x >> 4;

    float acc[4][4];
#pragma unroll
    for (int i = 0; i < 4; i++)
#pragma unroll
        for (int j = 0; j < 4; j++) acc[i][j] = 0.f;

    for (int k0 = 0; k0 < K; k0 += 16) {
#pragma unroll
        for (int i = threadIdx.x; i < 64*16; i += 256) {
            int m = i >> 4, kk = i & 15;
            As[m][kk] = A[(size_t)(bm + m) * K + k0 + kk];
        }
#pragma unroll
        for (int i = threadIdx.x; i < 16*64; i += 256) {
            int kk = i >> 6, n = i & 63;
            Bs[kk][n] = B[(size_t)(k0 + kk) * N + bn + n];
        }
        __syncthreads();
#pragma unroll
        for (int kk = 0; kk < 16; kk++) {
            float a[4], b[4];
#pragma unroll
            for (int i = 0; i < 4; i++) a[i] = As[ty*4 + i][kk];
#pragma unroll
            for (int j = 0; j < 4; j++) b[j] = Bs[kk][tx*4 + j];
#pragma unroll
            for (int i = 0; i < 4; i++)
#pragma unroll
                for (int j = 0; j < 4; j++) acc[i][j] = fmaf(a[i], b[j], acc[i][j]);
        }
        __syncthreads();
    }
#pragma unroll
    for (int i = 0; i < 4; i++) {
        int row = bm + ty*4 + i;
#pragma unroll
        for (int j = 0; j < 4; j++) {
            int col = bn + tx*4 + j;
            C[(size_t)row * N + col] = acc[i][j] + bias[col];
        }
    }
}

// ---------------------------------------------------------------------------
// RoPE in place. Tensor viewed as [MR rows][nheads*64 cols]. One thread per
// (row, head, i) rotation pair, i in [0,32).
// angle = fp32((t+1) * fp32(10000^(-2i/64))), sin/cos evaluated in double to
// be immune to --use_fast_math's __sincosf at large angles (up to ~2048 rad).
// ---------------------------------------------------------------------------
__global__ void rope_kernel(float* __restrict__ x, int nheads) {
    int idx = blockIdx.x * blockDim.x + threadIdx.x;
    int total = MR * nheads * 32;
    if (idx >= total) return;
    int i = idx & 31;
    int h = (idx >> 5) % nheads;
    int r = idx / (32 * nheads);
    int t = r & (Tn - 1);
    // theta computed in double, rounded to fp32 (matches jnp.power fp32 value)
    float theta = (float)pow(10000.0, -(2.0 * (double)i) / 64.0);
    float ang = __fmul_rn((float)(t + 1), theta);   // fp32 angle, as reference
    double cd, sd;
    sincos((double)ang, &sd, &cd);
    float c = (float)cd, s = (float)sd;
    float* p = x + (size_t)r * (nheads * 64) + h * 64;
    float x1 = p[i], x2 = p[i + 32];
    p[i]      = x1 * c - x2 * s;
    p[i + 32] = x2 * c + x1 * s;
}

// ---------------------------------------------------------------------------
// Causal attention logits: S[q,k] = (Q·K)/8, masked to -inf for k>q.
// grid: (32 heads = b*16+hq, qtile, ktile). Upper-triangular tiles skipped.
// att layout (B, G, HKV, T, T): head slot = b*16 + g*4 + hkv, hq = hkv*4 + g.
// ---------------------------------------------------------------------------
__global__ void scores_kernel(const float* __restrict__ q, const float* __restrict__ k,
                              float* __restrict__ att) {
    const int qt = blockIdx.y, kt = blockIdx.z;
    if (kt > qt) return;
    const int head = blockIdx.x;
    const int b = head >> 4, hq = head & 15;
    const int hkv = hq >> 2, g = hq & 3;

    __shared__ float Qs[64][65];
    __shared__ float Ks[64][65];

    const float* qbase = q + ((size_t)b * Tn + qt * 64) * En + hq * 64;
    const float* kbase = k + ((size_t)b * Tn + kt * 64) * KVW + hkv * 64;

#pragma unroll
    for (int i = threadIdx.x; i < 64*64; i += 256) {
        int m = i >> 6, d = i & 63;
        Qs[m][d] = qbase[(size_t)m * En + d];
        Ks[m][d] = kbase[(size_t)m * KVW + d];
    }
    __syncthreads();

    const int tx = threadIdx.x & 15, ty = threadIdx.x >> 4;
    float acc[4][4];
#pragma unroll
    for (int i = 0; i < 4; i++)
#pragma unroll
        for (int j = 0; j < 4; j++) acc[i][j] = 0.f;

#pragma unroll 16
    for (int d = 0; d < 64; d++) {
        float a[4], bb[4];
#pragma unroll
        for (int i = 0; i < 4; i++) a[i] = Qs[ty*4 + i][d];
#pragma unroll
        for (int j = 0; j < 4; j++) bb[j] = Ks[tx*4 + j][d];
#pragma unroll
        for (int i = 0; i < 4; i++)
#pragma unroll
            for (int j = 0; j < 4; j++) acc[i][j] = fmaf(a[i], bb[j], acc[i][j]);
    }

    float* obase = att + ((size_t)(b*16 + g*4 + hkv) * Tn + qt * 64) * Tn + kt * 64;
#pragma unroll
    for (int i = 0; i < 4; i++) {
        int qg = qt*64 + ty*4 + i;
#pragma unroll
        for (int j = 0; j < 4; j++) {
            int kg = kt*64 + tx*4 + j;
            float v = (kg > qg) ? NEG_INF : acc[i][j] * 0.125f;
            obase[(size_t)(ty*4 + i) * Tn + (tx*4 + j)] = v;
        }
    }
}

// ---------------------------------------------------------------------------
// Row softmax, in place over att rows. One block per row. Valid length = q+1;
// masked tail written as exact 0 (matches softmax of -inf; output region is
// poisoned so it must be written).
// ---------------------------------------------------------------------------
__global__ void softmax_kernel(float* __restrict__ att) {
    const int rid = blockIdx.x;          // 0 .. B*16*T-1, att-layout order
    const int qpos = rid & (Tn - 1);
    const int L = qpos + 1;
    float* row = att + (size_t)rid * Tn;

    __shared__ float buf[Tn];
    __shared__ float red[256];
    const int tid = threadIdx.x;

    float m = NEG_INF;
    for (int k = tid; k < L; k += 256) {
        float v = row[k];
        buf[k] = v;
        m = fmaxf(m, v);
    }
    red[tid] = m; __syncthreads();
    for (int s = 128; s > 0; s >>= 1) {
        if (tid < s) red[tid] = fmaxf(red[tid], red[tid + s]);
        __syncthreads();
    }
    m = red[0]; __syncthreads();

    float sum = 0.f;
    for (int k = tid; k < L; k += 256) {
        float e = expf(buf[k] - m);
        buf[k] = e;
        sum += e;
    }
    red[tid] = sum; __syncthreads();
    for (int s = 128; s > 0; s >>= 1) {
        if (tid < s) red[tid] += red[tid + s];
        __syncthreads();
    }
    const float inv = 1.f / red[0];

    for (int k = tid; k < Tn; k += 256) {
        row[k] = (k < L) ? buf[k] * inv : 0.f;
    }
}

// ---------------------------------------------------------------------------
// y = att @ V per head. grid: (32 heads, 32 qtiles). Only causal k-range.
// ---------------------------------------------------------------------------
__global__ void av_kernel(const float* __restrict__ att, const float* __restrict__ v,
                          float* __restrict__ y) {
    const int head = blockIdx.x, qt = blockIdx.y;
    const int b = head >> 4, hq = head & 15;
    const int hkv = hq >> 2, g = hq & 3;

    __shared__ float As[64][33];   // [q][kk]
    __shared__ float Vs[32][64];   // [kk][d]

    const float* abase = att + ((size_t)(b*16 + g*4 + hkv) * Tn + qt * 64) * Tn;
    const float* vbase = v + (size_t)b * Tn * KVW + hkv * 64;

    const int tx = threadIdx.x & 15, ty = threadIdx.x >> 4;
    float acc[4][4];
#pragma unroll
    for (int i = 0; i < 4; i++)
#pragma unroll
        for (int j = 0; j < 4; j++) acc[i][j] = 0.f;

    const int kend = (qt + 1) * 64;   // causal: weights beyond are 0
    for (int k0 = 0; k0 < kend; k0 += 32) {
#pragma unroll
        for (int i = threadIdx.x; i < 64*32; i += 256) {
            int m = i >> 5, kk = i & 31;
            As[m][kk] = abase[(size_t)m * Tn + k0 + kk];
        }
#pragma unroll
        for (int i = threadIdx.x; i < 32*64; i += 256) {
            int kk = i >> 6, n = i & 63;
            Vs[kk][n] = vbase[(size_t)(k0 + kk) * KVW + n];
        }
        __syncthreads();
#pragma unroll
        for (int kk = 0; kk < 32; kk++) {
            float a[4], bb[4];
#pragma unroll
            for (int i = 0; i < 4; i++) a[i] = As[ty*4 + i][kk];
#pragma unroll
            for (int j = 0; j < 4; j++) bb[j] = Vs[kk][tx*4 + j];
#pragma unroll
            for (int i = 0; i < 4; i++)
#pragma unroll
                for (int j = 0; j < 4; j++) acc[i][j] = fmaf(a[i], bb[j], acc[i][j]);
        }
        __syncthreads();
    }
#pragma unroll
    for (int i = 0; i < 4; i++) {
        int row = b * Tn + qt*64 + ty*4 + i;
#pragma unroll
        for (int j = 0; j < 4; j++) {
            y[(size_t)row * En + hq*64 + tx*4 + j] = acc[i][j];
        }
    }
}

// ---------------------------------------------------------------------------
extern "C" void kernel_launch(void* const* d_in, const int* in_sizes, int n_in,
                              void* d_out, int out_size) {
    const float* x  = (const float*)d_in[0];
    // d_in[1] = mask (int32) — static causal, unused
    const float* Wq = (const float*)d_in[2];
    const float* bq = (const float*)d_in[3];
    const float* Wk = (const float*)d_in[4];
    const float* bk = (const float*)d_in[5];
    const float* Wv = (const float*)d_in[6];
    const float* bv = (const float*)d_in[7];
    const float* Wo = (const float*)d_in[8];
    const float* bo = (const float*)d_in[9];

    float *pq, *pk, *pv, *py, *patt;
    cudaGetSymbolAddress((void**)&pq, g_q);
    cudaGetSymbolAddress((void**)&pk, g_k);
    cudaGetSymbolAddress((void**)&pv, g_v);
    cudaGetSymbolAddress((void**)&py, g_y);
    cudaGetSymbolAddress((void**)&patt, g_att);

    float* out = (float*)d_out;
    // Output layout detection — NEVER compute an out-of-range pointer.
    //  * out_size >= y+att: both outputs concatenated in d_out.
    //  * out_size == att only: att lives in d_out, no y output.
    //  * otherwise (e.g. y only): att goes to device-global scratch.
    float* y_out = nullptr;
    float* att;
    long long osz = (long long)out_size;
    if (osz >= (long long)YELEMS + ATTELEMS) {
        y_out = out;
        att = out + YELEMS;
    } else if (osz == ATTELEMS) {
        att = out;                 // att-only output
    } else {
        y_out = out;               // y-only output; att is scratch
        att = patt;
    }

    // 1) Projections
    sgemm_bias<<<dim3(En/64,  MR/64), 256>>>(x, Wq, bq, pq, MR, En,  En);
    sgemm_bias<<<dim3(KVW/64, MR/64), 256>>>(x, Wk, bk, pk, MR, KVW, En);
    sgemm_bias<<<dim3(KVW/64, MR/64), 256>>>(x, Wv, bv, pv, MR, KVW, En);

    // 2) RoPE on q and k
    rope_kernel<<<(MR*HQn*32  + 255)/256, 256>>>(pq, HQn);
    rope_kernel<<<(MR*HKVn*32 + 255)/256, 256>>>(pk, HKVn);

    // 3) Causal logits
    scores_kernel<<<dim3(Bn*HQn, Tn/64, Tn/64), 256>>>(pq, pk, att);

    // 4) Row softmax in place (also zero-fills masked tail)
    softmax_kernel<<<Bn*HQn*Tn, 256>>>(att);

    // 5) y = att @ V
    av_kernel<<<dim3(Bn*HQn, Tn/64), 256>>>(att, pv, py);

    // 6) Output projection
    if (y_out) {
        sgemm_bias<<<dim3(En/64, MR/64), 256>>>(py, Wo, bo, y_out, MR, En, En);
    }
}

// round 9
// speedup vs baseline: 1.5178x; 1.5178x over previous
#include <cuda_runtime.h>
#include <math.h>

// Problem constants
#define Bn   2
#define Tn   2048
#define En   1024
#define HQn  16
#define HKVn 4
#define Dn   64
#define Gn   4
#define MR   (Bn*Tn)            // 4096 rows
#define KVW  (HKVn*Dn)          // 256
#define YELEMS   (MR*En)                         // 4,194,304
#define ATTELEMS (134217728LL)                   // B*G*HKV*T*T

// Scratch (static device globals: allocation-free at run time)
__device__ float g_q[MR*En];
__device__ float g_k[MR*KVW];
__device__ float g_v[MR*KVW];
__device__ float g_y[MR*En];
// Full attention-matrix scratch for when d_out does NOT include att_weights.
__device__ float g_att[134217728];
// RoPE trig tables: [t][i], t in [0,2048), i in [0,32)
__device__ float g_cos[Tn*32];
__device__ float g_sin[Tn*32];

#define NEG_INF __int_as_float(0xff800000)

// ---------------------------------------------------------------------------
// Fill RoPE trig tables. 65536 threads, one double sincos each.
// angle = fp32((t+1) * fp32(10000^(-2i/64))), trig in double for accuracy at
// angles up to ~2048 rad (immune to --use_fast_math's __sincosf).
// ---------------------------------------------------------------------------
__global__ void fill_trig_kernel() {
    int idx = blockIdx.x * blockDim.x + threadIdx.x;
    if (idx >= Tn * 32) return;
    int i = idx & 31;
    int t = idx >> 5;
    float theta = (float)pow(10000.0, -(2.0 * (double)i) / 64.0);
    float ang = __fmul_rn((float)(t + 1), theta);   // fp32 angle, as reference
    double cd, sd;
    sincos((double)ang, &sd, &cd);
    g_cos[idx] = (float)cd;
    g_sin[idx] = (float)sd;
}

// ---------------------------------------------------------------------------
// SGEMM + bias: C[M,N] = A[M,K] @ B[K,N] + bias[N]
// 128x128 tile, BK=16, 256 threads, 8x8 micro-tile, float4 smem loads.
// Requires M%128==0, N%128==0, K%16==0 (true for all four projections).
// As stored transposed [kk][m] with +4 pad to cut STS bank conflicts.
// ---------------------------------------------------------------------------
__global__ void sgemm_bias(const float* __restrict__ A, const float* __restrict__ B,
                           const float* __restrict__ bias, float* __restrict__ C,
                           int M, int N, int K) {
    __shared__ float As[16][132];   // [kk][m], padded
    __shared__ float Bs[16][128];   // [kk][n]
    const int bm = blockIdx.y * 128;
    const int bn = blockIdx.x * 128;
    const int tid = threadIdx.x;
    const int tx = tid & 15;        // n-dim, 8 cols each
    const int ty = tid >> 4;        // m-dim, 8 rows each

    float acc[8][8];
#pragma unroll
    for (int i = 0; i < 8; i++)
#pragma unroll
        for (int j = 0; j < 8; j++) acc[i][j] = 0.f;

    for (int k0 = 0; k0 < K; k0 += 16) {
        // A tile: 128x16 = 512 float4 loads, transposed store into As[kk][m]
#pragma unroll
        for (int l = 0; l < 2; l++) {
            int j = tid + l * 256;
            int row = j >> 2, c4 = (j & 3) * 4;
            float4 v = *(const float4*)&A[(size_t)(bm + row) * K + k0 + c4];
            As[c4 + 0][row] = v.x;
            As[c4 + 1][row] = v.y;
            As[c4 + 2][row] = v.z;
            As[c4 + 3][row] = v.w;
        }
        // B tile: 16x128 = 512 float4 loads, direct store
#pragma unroll
        for (int l = 0; l < 2; l++) {
            int j = tid + l * 256;
            int row = j >> 5, c4 = (j & 31) * 4;
            *(float4*)&Bs[row][c4] = *(const float4*)&B[(size_t)(k0 + row) * N + bn + c4];
        }
        __syncthreads();
#pragma unroll
        for (int kk = 0; kk < 16; kk++) {
            float a[8], b[8];
            *(float4*)&a[0] = *(const float4*)&As[kk][ty * 8];
            *(float4*)&a[4] = *(const float4*)&As[kk][ty * 8 + 4];
            *(float4*)&b[0] = *(const float4*)&Bs[kk][tx * 8];
            *(float4*)&b[4] = *(const float4*)&Bs[kk][tx * 8 + 4];
#pragma unroll
            for (int i = 0; i < 8; i++)
#pragma unroll
                for (int j = 0; j < 8; j++) acc[i][j] = fmaf(a[i], b[j], acc[i][j]);
        }
        __syncthreads();
    }

    // Epilogue: add bias, vectorized stores
    float bb[8];
#pragma unroll
    for (int j = 0; j < 8; j++) bb[j] = bias[bn + tx * 8 + j];
#pragma unroll
    for (int i = 0; i < 8; i++) {
        int row = bm + ty * 8 + i;
        float4 v0, v1;
        v0.x = acc[i][0] + bb[0]; v0.y = acc[i][1] + bb[1];
        v0.z = acc[i][2] + bb[2]; v0.w = acc[i][3] + bb[3];
        v1.x = acc[i][4] + bb[4]; v1.y = acc[i][5] + bb[5];
        v1.z = acc[i][6] + bb[6]; v1.w = acc[i][7] + bb[7];
        *(float4*)&C[(size_t)row * N + bn + tx * 8]     = v0;
        *(float4*)&C[(size_t)row * N + bn + tx * 8 + 4] = v1;
    }
}

// ---------------------------------------------------------------------------
// RoPE in place using precomputed trig tables. One thread per (row, head, i)
// rotation pair, i in [0,32).
// ---------------------------------------------------------------------------
__global__ void rope_kernel(float* __restrict__ x, int nheads) {
    int idx = blockIdx.x * blockDim.x + threadIdx.x;
    int total = MR * nheads * 32;
    if (idx >= total) return;
    int i = idx & 31;
    int h = (idx >> 5) % nheads;
    int r = idx / (32 * nheads);
    int t = r & (Tn - 1);
    float c = g_cos[(t << 5) + i];
    float s = g_sin[(t << 5) + i];
    float* p = x + (size_t)r * (nheads * 64) + h * 64;
    float x1 = p[i], x2 = p[i + 32];
    p[i]      = x1 * c - x2 * s;
    p[i + 32] = x2 * c + x1 * s;
}

// ---------------------------------------------------------------------------
// Causal attention logits: S[q,k] = (Q·K)/8, masked to -inf for k>q.
// grid: (32 heads = b*16+hq, qtile, ktile). Upper-triangular tiles skipped.
// att layout (B, G, HKV, T, T): head slot = b*16 + g*4 + hkv, hq = hkv*4 + g.
// ---------------------------------------------------------------------------
__global__ void scores_kernel(const float* __restrict__ q, const float* __restrict__ k,
                              float* __restrict__ att) {
    const int qt = blockIdx.y, kt = blockIdx.z;
    if (kt > qt) return;
    const int head = blockIdx.x;
    const int b = head >> 4, hq = head & 15;
    const int hkv = hq >> 2, g = hq & 3;

    __shared__ float Qs[64][65];
    __shared__ float Ks[64][65];

    const float* qbase = q + ((size_t)b * Tn + qt * 64) * En + hq * 64;
    const float* kbase = k + ((size_t)b * Tn + kt * 64) * KVW + hkv * 64;

#pragma unroll
    for (int i = threadIdx.x; i < 64*64; i += 256) {
        int m = i >> 6, d = i & 63;
        Qs[m][d] = qbase[(size_t)m * En + d];
        Ks[m][d] = kbase[(size_t)m * KVW + d];
    }
    __syncthreads();

    const int tx = threadIdx.x & 15, ty = threadIdx.x >> 4;
    float acc[4][4];
#pragma unroll
    for (int i = 0; i < 4; i++)
#pragma unroll
        for (int j = 0; j < 4; j++) acc[i][j] = 0.f;

#pragma unroll 16
    for (int d = 0; d < 64; d++) {
        float a[4], bb[4];
#pragma unroll
        for (int i = 0; i < 4; i++) a[i] = Qs[ty*4 + i][d];
#pragma unroll
        for (int j = 0; j < 4; j++) bb[j] = Ks[tx*4 + j][d];
#pragma unroll
        for (int i = 0; i < 4; i++)
#pragma unroll
            for (int j = 0; j < 4; j++) acc[i][j] = fmaf(a[i], bb[j], acc[i][j]);
    }

    float* obase = att + ((size_t)(b*16 + g*4 + hkv) * Tn + qt * 64) * Tn + kt * 64;
#pragma unroll
    for (int i = 0; i < 4; i++) {
        int qg = qt*64 + ty*4 + i;
#pragma unroll
        for (int j = 0; j < 4; j++) {
            int kg = kt*64 + tx*4 + j;
            float v = (kg > qg) ? NEG_INF : acc[i][j] * 0.125f;
            obase[(size_t)(ty*4 + i) * Tn + (tx*4 + j)] = v;
        }
    }
}

// ---------------------------------------------------------------------------
// Row softmax, in place over att rows. One block per row. Valid length = q+1;
// masked tail written as exact 0.
// ---------------------------------------------------------------------------
__global__ void softmax_kernel(float* __restrict__ att) {
    const int rid = blockIdx.x;          // 0 .. B*16*T-1, att-layout order
    const int qpos = rid & (Tn - 1);
    const int L = qpos + 1;
    float* row = att + (size_t)rid * Tn;

    __shared__ float buf[Tn];
    __shared__ float red[256];
    const int tid = threadIdx.x;

    float m = NEG_INF;
    for (int k = tid; k < L; k += 256) {
        float v = row[k];
        buf[k] = v;
        m = fmaxf(m, v);
    }
    red[tid] = m; __syncthreads();
    for (int s = 128; s > 0; s >>= 1) {
        if (tid < s) red[tid] = fmaxf(red[tid], red[tid + s]);
        __syncthreads();
    }
    m = red[0]; __syncthreads();

    float sum = 0.f;
    for (int k = tid; k < L; k += 256) {
        float e = expf(buf[k] - m);
        buf[k] = e;
        sum += e;
    }
    red[tid] = sum; __syncthreads();
    for (int s = 128; s > 0; s >>= 1) {
        if (tid < s) red[tid] += red[tid + s];
        __syncthreads();
    }
    const float inv = 1.f / red[0];

    for (int k = tid; k < Tn; k += 256) {
        row[k] = (k < L) ? buf[k] * inv : 0.f;
    }
}

// ---------------------------------------------------------------------------
// y = att @ V per head. grid: (32 heads, 32 qtiles). Only causal k-range.
// ---------------------------------------------------------------------------
__global__ void av_kernel(const float* __restrict__ att, const float* __restrict__ v,
                          float* __restrict__ y) {
    const int head = blockIdx.x, qt = blockIdx.y;
    const int b = head >> 4, hq = head & 15;
    const int hkv = hq >> 2, g = hq & 3;

    __shared__ float As[64][33];   // [q][kk]
    __shared__ float Vs[32][64];   // [kk][d]

    const float* abase = att + ((size_t)(b*16 + g*4 + hkv) * Tn + qt * 64) * Tn;
    const float* vbase = v + (size_t)b * Tn * KVW + hkv * 64;

    const int tx = threadIdx.x & 15, ty = threadIdx.x >> 4;
    float acc[4][4];
#pragma unroll
    for (int i = 0; i < 4; i++)
#pragma unroll
        for (int j = 0; j < 4; j++) acc[i][j] = 0.f;

    const int kend = (qt + 1) * 64;   // causal: weights beyond are 0
    for (int k0 = 0; k0 < kend; k0 += 32) {
#pragma unroll
        for (int i = threadIdx.x; i < 64*32; i += 256) {
            int m = i >> 5, kk = i & 31;
            As[m][kk] = abase[(size_t)m * Tn + k0 + kk];
        }
#pragma unroll
        for (int i = threadIdx.x; i < 32*64; i += 256) {
            int kk = i >> 6, n = i & 63;
            Vs[kk][n] = vbase[(size_t)(k0 + kk) * KVW + n];
        }
        __syncthreads();
#pragma unroll
        for (int kk = 0; kk < 32; kk++) {
            float a[4], bb[4];
#pragma unroll
            for (int i = 0; i < 4; i++) a[i] = As[ty*4 + i][kk];
#pragma unroll
            for (int j = 0; j < 4; j++) bb[j] = Vs[kk][tx*4 + j];
#pragma unroll
            for (int i = 0; i < 4; i++)
#pragma unroll
                for (int j = 0; j < 4; j++) acc[i][j] = fmaf(a[i], bb[j], acc[i][j]);
        }
        __syncthreads();
    }
#pragma unroll
    for (int i = 0; i < 4; i++) {
        int row = b * Tn + qt*64 + ty*4 + i;
#pragma unroll
        for (int j = 0; j < 4; j++) {
            y[(size_t)row * En + hq*64 + tx*4 + j] = acc[i][j];
        }
    }
}

// ---------------------------------------------------------------------------
extern "C" void kernel_launch(void* const* d_in, const int* in_sizes, int n_in,
                              void* d_out, int out_size) {
    const float* x  = (const float*)d_in[0];
    // d_in[1] = mask (int32) — static causal, unused
    const float* Wq = (const float*)d_in[2];
    const float* bq = (const float*)d_in[3];
    const float* Wk = (const float*)d_in[4];
    const float* bk = (const float*)d_in[5];
    const float* Wv = (const float*)d_in[6];
    const float* bv = (const float*)d_in[7];
    const float* Wo = (const float*)d_in[8];
    const float* bo = (const float*)d_in[9];

    float *pq, *pk, *pv, *py, *patt;
    cudaGetSymbolAddress((void**)&pq, g_q);
    cudaGetSymbolAddress((void**)&pk, g_k);
    cudaGetSymbolAddress((void**)&pv, g_v);
    cudaGetSymbolAddress((void**)&py, g_y);
    cudaGetSymbolAddress((void**)&patt, g_att);

    float* out = (float*)d_out;
    // Output layout detection — NEVER compute an out-of-range pointer.
    float* y_out = nullptr;
    float* att;
    long long osz = (long long)out_size;
    if (osz >= (long long)YELEMS + ATTELEMS) {
        y_out = out;
        att = out + YELEMS;
    } else if (osz == ATTELEMS) {
        att = out;                 // att-only output
    } else {
        y_out = out;               // y-only output; att is scratch
        att = patt;
    }

    // 0) RoPE trig tables
    fill_trig_kernel<<<(Tn*32 + 255)/256, 256>>>();

    // 1) Projections (128x128 tiles; all dims divide evenly)
    sgemm_bias<<<dim3(En/128,  MR/128), 256>>>(x, Wq, bq, pq, MR, En,  En);
    sgemm_bias<<<dim3(KVW/128, MR/128), 256>>>(x, Wk, bk, pk, MR, KVW, En);
    sgemm_bias<<<dim3(KVW/128, MR/128), 256>>>(x, Wv, bv, pv, MR, KVW, En);

    // 2) RoPE on q and k (table-driven)
    rope_kernel<<<(MR*HQn*32  + 255)/256, 256>>>(pq, HQn);
    rope_kernel<<<(MR*HKVn*32 + 255)/256, 256>>>(pk, HKVn);

    // 3) Causal logits
    scores_kernel<<<dim3(Bn*HQn, Tn/64, Tn/64), 256>>>(pq, pk, att);

    // 4) Row softmax in place (also zero-fills masked tail)
    softmax_kernel<<<Bn*HQn*Tn, 256>>>(att);

    // 5) y = att @ V
    av_kernel<<<dim3(Bn*HQn, Tn/64), 256>>>(att, pv, py);

    // 6) Output projection
    if (y_out) {
        sgemm_bias<<<dim3(En/128, MR/128), 256>>>(py, Wo, bo, y_out, MR, En, En);
    }
}